// round 5
// baseline (speedup 1.0000x reference)
#include <cuda_runtime.h>
#include <cuda_bf16.h>

// Problem constants (fixed shapes per reference setup_inputs)
#define BATCH 32
#define IMG_H 512
#define IMG_W 512
#define IMG_C 3
#define KPTS 16
#define NE 19                 // K + 3
#define NPIX (IMG_H * IMG_W)  // 262144
#define TPB 256               // threads per block == pixels per block

// Dynamic smem layout (floats):
//   [0, COEFF)                 : s_coeff[(b*2+p)*NE + e]
//   [COEFF, COEFF+BN)          : s_x[b*TPB + q]  (pixel-space x)
//   [COEFF+BN, COEFF+2*BN)     : s_y[b*TPB + q]  (pixel-space y)
#define COEFF (BATCH * 2 * NE)
#define BN    (BATCH * TPB)
#define SMEM_FLOATS (COEFF + 2 * BN)

// Numerics contract (replicates the reference's XLA:GPU fp32 semantics;
// validated rel_err = 9.49e-4 in round 4 — do not perturb):
//  - einsum1: mul-then-add, NO contraction, ascending k.
//  - einsum2: sequential ascending FFMA, init 0.
//  - bilinear blend: left-assoc mul/add, no contraction.
__global__ __launch_bounds__(TPB) void tps_warp_kernel(
    const float* __restrict__ image,         // (B, H, W, C)
    const float* __restrict__ dest_offsets,  // (B, 2*K)
    const float* __restrict__ right_mat,     // (NE, NPIX)
    const float* __restrict__ L_inv,         // (NE, NE)
    const float* __restrict__ src,           // (2, K)
    float* __restrict__ out)                 // (B, H, W, C)
{
    extern __shared__ float sm[];
    float* s_coeff = sm;
    float* s_x = sm + COEFF;
    float* s_y = sm + COEFF + BN;

    const int tid = threadIdx.x;

    // --- einsum1: coeff[b][p][e] = sum_k (src[p][k]+off[b][p][k]) * L_inv[e][3+k]
    for (int i = tid; i < COEFF; i += TPB) {
        const int e  = i % NE;
        const int bp = i / NE;
        const int p  = bp & 1;
        const int b  = bp >> 1;
        float acc = 0.0f;
#pragma unroll
        for (int k = 0; k < KPTS; k++) {
            const float d = __fadd_rn(src[p * KPTS + k],
                                      dest_offsets[b * (2 * KPTS) + p * KPTS + k]);
            acc = __fadd_rn(acc, __fmul_rn(d, L_inv[e * NE + 3 + k]));
        }
        s_coeff[i] = acc;
    }
    __syncthreads();

    // --- phase 1: per-pixel coordinates for all batches (thread owns one n)
    const int n = blockIdx.x * TPB + tid;

    float rm[NE];
#pragma unroll
    for (int e = 0; e < NE; e++) rm[e] = __ldg(&right_mat[e * NPIX + n]);

    const float fw = (float)IMG_W;
    const float fh = (float)IMG_H;

#pragma unroll 4
    for (int b = 0; b < BATCH; b++) {
        const float* cx = &s_coeff[(b * 2 + 0) * NE];
        const float* cy = &s_coeff[(b * 2 + 1) * NE];
        float xs = 0.0f, ys = 0.0f;
#pragma unroll
        for (int e = 0; e < NE; e++) {
            xs = fmaf(cx[e], rm[e], xs);
            ys = fmaf(cy[e], rm[e], ys);
        }
        s_x[b * TPB + tid] = __fmul_rn(__fmul_rn(0.5f, __fadd_rn(xs, 1.0f)), fw);
        s_y[b * TPB + tid] = __fmul_rn(__fmul_rn(0.5f, __fadd_rn(ys, 1.0f)), fh);
    }
    __syncthreads();

    // --- phase 2: gather + store with channel-split mapping.
    // Consecutive lanes own consecutive output floats -> coalesced taps/stores.
    int qi[3], ci[3];
#pragma unroll
    for (int i = 0; i < 3; i++) {
        const int f = i * TPB + tid;   // 0..767: float index in block's row chunk
        qi[i] = f / 3;                 // pixel within block
        ci[i] = f - qi[i] * 3;         // channel
    }
    const size_t base3 = (size_t)blockIdx.x * TPB * IMG_C;

    for (int b = 0; b < BATCH; b++) {
        const float* img = image + (size_t)b * (NPIX * IMG_C);
        float* ob = out + (size_t)b * (NPIX * IMG_C) + base3;
        const float* bx = &s_x[b * TPB];
        const float* by = &s_y[b * TPB];

#pragma unroll
        for (int i = 0; i < 3; i++) {
            const int q = qi[i];
            const int c = ci[i];
            const float x = bx[q];
            const float y = by[q];

            // trunc-toward-zero matches jnp astype(int32)
            const int x0 = (int)x;
            const int y0 = (int)y;
            const int x0c = min(max(x0, 0), IMG_W - 1);
            const int x1c = min(max(x0 + 1, 0), IMG_W - 1);
            const int y0c = min(max(y0, 0), IMG_H - 1);
            const int y1c = min(max(y0 + 1, 0), IMG_H - 1);

            const float x0f = (float)x0c, x1f = (float)x1c;
            const float y0f = (float)y0c, y1f = (float)y1c;
            const float wa = __fmul_rn(__fadd_rn(x1f, -x), __fadd_rn(y1f, -y));
            const float wb = __fmul_rn(__fadd_rn(x1f, -x), __fadd_rn(y, -y0f));
            const float wc = __fmul_rn(__fadd_rn(x, -x0f), __fadd_rn(y1f, -y));
            const float wd = __fmul_rn(__fadd_rn(x, -x0f), __fadd_rn(y, -y0f));

            const int r0 = y0c * IMG_W;
            const int r1 = y1c * IMG_W;
            const float va = __ldg(img + (size_t)(r0 + x0c) * IMG_C + c);
            const float vb = __ldg(img + (size_t)(r1 + x0c) * IMG_C + c);
            const float vc = __ldg(img + (size_t)(r0 + x1c) * IMG_C + c);
            const float vd = __ldg(img + (size_t)(r1 + x1c) * IMG_C + c);

            // (((wa*va + wb*vb) + wc*vc) + wd*vd), no contraction
            float o = __fmul_rn(wa, va);
            o = __fadd_rn(o, __fmul_rn(wb, vb));
            o = __fadd_rn(o, __fmul_rn(wc, vc));
            o = __fadd_rn(o, __fmul_rn(wd, vd));
            ob[i * TPB + tid] = o;
        }
    }
}

extern "C" void kernel_launch(void* const* d_in, const int* in_sizes, int n_in,
                              void* d_out, int out_size) {
    const float* image        = (const float*)d_in[0];
    const float* dest_offsets = (const float*)d_in[1];
    const float* right_mat    = (const float*)d_in[2];
    const float* L_inv        = (const float*)d_in[3];
    const float* src          = (const float*)d_in[4];
    float* out = (float*)d_out;

    static bool attr_set = false;
    if (!attr_set) {
        cudaFuncSetAttribute(tps_warp_kernel,
                             cudaFuncAttributeMaxDynamicSharedMemorySize,
                             SMEM_FLOATS * sizeof(float));
        attr_set = true;
    }

    const int blocks = NPIX / TPB;  // 1024, exact
    tps_warp_kernel<<<blocks, TPB, SMEM_FLOATS * sizeof(float)>>>(
        image, dest_offsets, right_mat, L_inv, src, out);
}

// round 6
// speedup vs baseline: 1.3726x; 1.3726x over previous
#include <cuda_runtime.h>
#include <cuda_bf16.h>

// Problem constants (fixed shapes per reference setup_inputs)
#define BATCH 32
#define IMG_H 512
#define IMG_W 512
#define IMG_C 3
#define KPTS 16
#define NE 19                 // K + 3
#define NPIX (IMG_H * IMG_W)  // 262144
#define TPB 256               // threads per block == pixels per block
#define BCHUNK 8              // batches staged in smem per phase
#define NCHUNK (BATCH / BCHUNK)

// Dynamic smem layout (floats):
//   [0, COEFF)                     : s_coeff[(b*2+p)*NE + e]
//   [COEFF, COEFF+CN)              : s_x[bc*TPB + q]
//   [COEFF+CN, COEFF+2*CN)         : s_y[bc*TPB + q]
#define COEFF (BATCH * 2 * NE)
#define CN    (BCHUNK * TPB)
#define SMEM_FLOATS (COEFF + 2 * CN)

// Numerics contract (replicates reference XLA:GPU fp32 semantics; validated
// rel_err = 9.489e-4 — do not perturb):
//  - einsum1: mul-then-add, NO contraction, ascending k.
//  - einsum2: sequential ascending FFMA, init 0.
//  - bilinear blend: left-assoc mul/add, no contraction.
__global__ __launch_bounds__(TPB, 6) void tps_warp_kernel(
    const float* __restrict__ image,         // (B, H, W, C)
    const float* __restrict__ dest_offsets,  // (B, 2*K)
    const float* __restrict__ right_mat,     // (NE, NPIX)
    const float* __restrict__ L_inv,         // (NE, NE)
    const float* __restrict__ src,           // (2, K)
    float* __restrict__ out)                 // (B, H, W, C)
{
    extern __shared__ float sm[];
    float* s_coeff = sm;
    float* s_x = sm + COEFF;
    float* s_y = sm + COEFF + CN;

    const int tid = threadIdx.x;
    const int n = blockIdx.x * TPB + tid;       // grid point this thread owns in phase 1
    const int base3 = blockIdx.x * (TPB * IMG_C);

    // --- einsum1: coeff[b][p][e] = sum_k (src[p][k]+off[b][p][k]) * L_inv[e][3+k]
    for (int i = tid; i < COEFF; i += TPB) {
        const int e  = i % NE;
        const int bp = i / NE;
        const int p  = bp & 1;
        const int b  = bp >> 1;
        float acc = 0.0f;
#pragma unroll
        for (int k = 0; k < KPTS; k++) {
            const float d = __fadd_rn(src[p * KPTS + k],
                                      dest_offsets[b * (2 * KPTS) + p * KPTS + k]);
            acc = __fadd_rn(acc, __fmul_rn(d, L_inv[e * NE + 3 + k]));
        }
        s_coeff[i] = acc;
    }
    __syncthreads();

    // channel-split mapping for phase 2: consecutive lanes own consecutive
    // output floats -> fully coalesced taps and stores.
    int qi[3], ci[3];
#pragma unroll
    for (int i = 0; i < 3; i++) {
        const int f = i * TPB + tid;
        qi[i] = f / 3;
        ci[i] = f - qi[i] * 3;
    }

    const float fw = (float)IMG_W;
    const float fh = (float)IMG_H;

    for (int ch = 0; ch < NCHUNK; ch++) {
        const int b0 = ch * BCHUNK;

        // --- phase 1: coords for BCHUNK batches (rm reloaded; L2-resident
        // after chunk 0, and its registers die at the sync below).
        {
            float rm[NE];
#pragma unroll
            for (int e = 0; e < NE; e++) rm[e] = __ldg(&right_mat[e * NPIX + n]);

#pragma unroll
            for (int bc = 0; bc < BCHUNK; bc++) {
                const float* cx = &s_coeff[((b0 + bc) * 2 + 0) * NE];
                const float* cy = &s_coeff[((b0 + bc) * 2 + 1) * NE];
                float xs = 0.0f, ys = 0.0f;
#pragma unroll
                for (int e = 0; e < NE; e++) {
                    xs = fmaf(cx[e], rm[e], xs);
                    ys = fmaf(cy[e], rm[e], ys);
                }
                s_x[bc * TPB + tid] = __fmul_rn(__fmul_rn(0.5f, __fadd_rn(xs, 1.0f)), fw);
                s_y[bc * TPB + tid] = __fmul_rn(__fmul_rn(0.5f, __fadd_rn(ys, 1.0f)), fh);
            }
        }
        __syncthreads();

        // --- phase 2: gather + store, channel-split
        for (int bc = 0; bc < BCHUNK; bc++) {
            const int b = b0 + bc;
            const float* img = image + b * (NPIX * IMG_C);
            float* ob = out + b * (NPIX * IMG_C) + base3;
            const float* bx = &s_x[bc * TPB];
            const float* by = &s_y[bc * TPB];

#pragma unroll
            for (int i = 0; i < 3; i++) {
                const int q = qi[i];
                const int c = ci[i];
                const float x = bx[q];
                const float y = by[q];

                // trunc-toward-zero matches jnp astype(int32)
                const int x0 = (int)x;
                const int y0 = (int)y;
                const int x0c = min(max(x0, 0), IMG_W - 1);
                const int x1c = min(max(x0 + 1, 0), IMG_W - 1);
                const int y0c = min(max(y0, 0), IMG_H - 1);
                const int y1c = min(max(y0 + 1, 0), IMG_H - 1);

                const float x0f = (float)x0c, x1f = (float)x1c;
                const float y0f = (float)y0c, y1f = (float)y1c;
                const float wa = __fmul_rn(__fadd_rn(x1f, -x), __fadd_rn(y1f, -y));
                const float wb = __fmul_rn(__fadd_rn(x1f, -x), __fadd_rn(y, -y0f));
                const float wc = __fmul_rn(__fadd_rn(x, -x0f), __fadd_rn(y1f, -y));
                const float wd = __fmul_rn(__fadd_rn(x, -x0f), __fadd_rn(y, -y0f));

                const int r0 = y0c * IMG_W;
                const int r1 = y1c * IMG_W;
                const float va = __ldg(img + (r0 + x0c) * IMG_C + c);
                const float vb = __ldg(img + (r1 + x0c) * IMG_C + c);
                const float vc = __ldg(img + (r0 + x1c) * IMG_C + c);
                const float vd = __ldg(img + (r1 + x1c) * IMG_C + c);

                // (((wa*va + wb*vb) + wc*vc) + wd*vd), no contraction
                float o = __fmul_rn(wa, va);
                o = __fadd_rn(o, __fmul_rn(wb, vb));
                o = __fadd_rn(o, __fmul_rn(wc, vc));
                o = __fadd_rn(o, __fmul_rn(wd, vd));
                ob[i * TPB + tid] = o;
            }
        }
        __syncthreads();
    }
}

extern "C" void kernel_launch(void* const* d_in, const int* in_sizes, int n_in,
                              void* d_out, int out_size) {
    const float* image        = (const float*)d_in[0];
    const float* dest_offsets = (const float*)d_in[1];
    const float* right_mat    = (const float*)d_in[2];
    const float* L_inv        = (const float*)d_in[3];
    const float* src          = (const float*)d_in[4];
    float* out = (float*)d_out;

    const int blocks = NPIX / TPB;  // 1024, exact
    tps_warp_kernel<<<blocks, TPB, SMEM_FLOATS * sizeof(float)>>>(
        image, dest_offsets, right_mat, L_inv, src, out);
}

// round 9
// speedup vs baseline: 1.5906x; 1.1588x over previous
#include <cuda_runtime.h>
#include <cuda_bf16.h>

// Problem constants (fixed shapes per reference setup_inputs)
#define BATCH 32
#define IMG_H 512
#define IMG_W 512
#define IMG_C 3
#define KPTS 16
#define NE 19                  // K + 3
#define NEP 20                 // padded coeff row (16B-aligned float4 reads)
#define NPIX (IMG_H * IMG_W)   // 262144
#define TPB 256                // pixels per chunk
#define BCHUNK 8               // batches per block
#define NGROUP (BATCH / BCHUNK)      // 4
#define NCHUNKS (NPIX / TPB)         // 1024
#define NUNITS (NCHUNKS * NGROUP)    // 4096 blocks: fine-grained, tail ~2-4%

// Numerics contract (replicates reference XLA:GPU fp32 semantics; validated
// rel_err = 9.489e-4 — do not perturb):
//  - einsum1: mul-then-add, NO contraction, ascending k.
//  - einsum2: sequential ascending FFMA, init 0  (e = 0..18 in order).
//  - bilinear blend: left-assoc mul/add, no contraction.
__global__ __launch_bounds__(TPB, 6) void tps_warp_kernel(
    const float* __restrict__ image,         // (B, H, W, C)
    const float* __restrict__ dest_offsets,  // (B, 2*K)
    const float* __restrict__ right_mat,     // (NE, NPIX)
    const float* __restrict__ L_inv,         // (NE, NE)
    const float* __restrict__ src,           // (2, K)
    float* __restrict__ out)                 // (B, H, W, C)
{
    __shared__ float  s_coeff[BCHUNK * 2 * NEP];  // this block's 8 batches, padded rows
    __shared__ float2 s_xy[BCHUNK * TPB];

    const int tid   = threadIdx.x;
    const int chunk = blockIdx.x >> 2;   // consecutive blocks share a chunk -> rm L2 reuse
    const int grp   = blockIdx.x & 3;
    const int n     = chunk * TPB + tid;
    const int b0    = grp * BCHUNK;

    // --- einsum1 for this block's 8 batches (tiny; inputs L2-resident):
    // coeff[b][p][e] = sum_k (src[p][k]+off[b][p][k]) * L_inv[e][3+k]
    for (int i = tid; i < BCHUNK * 2 * NEP; i += TPB) {
        const int e  = i % NEP;
        const int bp = i / NEP;
        const int p  = bp & 1;
        const int b  = b0 + (bp >> 1);
        float acc = 0.0f;
        if (e < NE) {
#pragma unroll
            for (int k = 0; k < KPTS; k++) {
                const float d = __fadd_rn(src[p * KPTS + k],
                                          dest_offsets[b * (2 * KPTS) + p * KPTS + k]);
                acc = __fadd_rn(acc, __fmul_rn(d, L_inv[e * NE + 3 + k]));
            }
        }
        s_coeff[i] = acc;
    }

    // channel-split mapping for phase 2
    int qi[3], ci[3];
#pragma unroll
    for (int i = 0; i < 3; i++) {
        const int f = i * TPB + tid;
        qi[i] = f / 3;
        ci[i] = f - qi[i] * 3;
    }

    const float fw = (float)IMG_W;
    const float fh = (float)IMG_H;

    __syncthreads();

    // --- phase 1: coords for the 8 batches (rm in registers, die at the sync)
    {
        float rm[NE];
#pragma unroll
        for (int e = 0; e < NE; e++) rm[e] = __ldg(&right_mat[e * NPIX + n]);

#pragma unroll 1
        for (int bc = 0; bc < BCHUNK; bc++) {
            const float4* cx4 = (const float4*)&s_coeff[(bc * 2 + 0) * NEP];
            const float4* cy4 = (const float4*)&s_coeff[(bc * 2 + 1) * NEP];
            const float4 x0v = cx4[0], x1v = cx4[1], x2v = cx4[2], x3v = cx4[3], x4v = cx4[4];
            const float4 y0v = cy4[0], y1v = cy4[1], y2v = cy4[2], y3v = cy4[3], y4v = cy4[4];

            // einsum2: sequential ascending FFMA, init 0 (e = 0..18)
            float xs = 0.0f, ys = 0.0f;
            xs = fmaf(x0v.x, rm[0], xs);  ys = fmaf(y0v.x, rm[0], ys);
            xs = fmaf(x0v.y, rm[1], xs);  ys = fmaf(y0v.y, rm[1], ys);
            xs = fmaf(x0v.z, rm[2], xs);  ys = fmaf(y0v.z, rm[2], ys);
            xs = fmaf(x0v.w, rm[3], xs);  ys = fmaf(y0v.w, rm[3], ys);
            xs = fmaf(x1v.x, rm[4], xs);  ys = fmaf(y1v.x, rm[4], ys);
            xs = fmaf(x1v.y, rm[5], xs);  ys = fmaf(y1v.y, rm[5], ys);
            xs = fmaf(x1v.z, rm[6], xs);  ys = fmaf(y1v.z, rm[6], ys);
            xs = fmaf(x1v.w, rm[7], xs);  ys = fmaf(y1v.w, rm[7], ys);
            xs = fmaf(x2v.x, rm[8], xs);  ys = fmaf(y2v.x, rm[8], ys);
            xs = fmaf(x2v.y, rm[9], xs);  ys = fmaf(y2v.y, rm[9], ys);
            xs = fmaf(x2v.z, rm[10], xs); ys = fmaf(y2v.z, rm[10], ys);
            xs = fmaf(x2v.w, rm[11], xs); ys = fmaf(y2v.w, rm[11], ys);
            xs = fmaf(x3v.x, rm[12], xs); ys = fmaf(y3v.x, rm[12], ys);
            xs = fmaf(x3v.y, rm[13], xs); ys = fmaf(y3v.y, rm[13], ys);
            xs = fmaf(x3v.z, rm[14], xs); ys = fmaf(y3v.z, rm[14], ys);
            xs = fmaf(x3v.w, rm[15], xs); ys = fmaf(y3v.w, rm[15], ys);
            xs = fmaf(x4v.x, rm[16], xs); ys = fmaf(y4v.x, rm[16], ys);
            xs = fmaf(x4v.y, rm[17], xs); ys = fmaf(y4v.y, rm[17], ys);
            xs = fmaf(x4v.z, rm[18], xs); ys = fmaf(y4v.z, rm[18], ys);

            const float x = __fmul_rn(__fmul_rn(0.5f, __fadd_rn(xs, 1.0f)), fw);
            const float y = __fmul_rn(__fmul_rn(0.5f, __fadd_rn(ys, 1.0f)), fh);
            s_xy[bc * TPB + tid] = make_float2(x, y);
        }
    }
    __syncthreads();

    // --- phase 2: gather + store, channel-split (coalesced taps/stores)
    const int base3 = chunk * (TPB * IMG_C);
#pragma unroll 1
    for (int bc = 0; bc < BCHUNK; bc++) {
        const int b = b0 + bc;
        const float* img = image + b * (NPIX * IMG_C);
        float* ob = out + b * (NPIX * IMG_C) + base3;
        const float2* bxy = &s_xy[bc * TPB];

#pragma unroll
        for (int i = 0; i < 3; i++) {
            const int q = qi[i];
            const int c = ci[i];
            const float2 xy = bxy[q];
            const float x = xy.x;
            const float y = xy.y;

            // trunc-toward-zero matches jnp astype(int32)
            const int x0 = (int)x;
            const int y0 = (int)y;
            const int x0c = min(max(x0, 0), IMG_W - 1);
            const int x1c = min(max(x0 + 1, 0), IMG_W - 1);
            const int y0c = min(max(y0, 0), IMG_H - 1);
            const int y1c = min(max(y0 + 1, 0), IMG_H - 1);

            const float x0f = (float)x0c, x1f = (float)x1c;
            const float y0f = (float)y0c, y1f = (float)y1c;
            const float wa = __fmul_rn(__fadd_rn(x1f, -x), __fadd_rn(y1f, -y));
            const float wb = __fmul_rn(__fadd_rn(x1f, -x), __fadd_rn(y, -y0f));
            const float wc = __fmul_rn(__fadd_rn(x, -x0f), __fadd_rn(y1f, -y));
            const float wd = __fmul_rn(__fadd_rn(x, -x0f), __fadd_rn(y, -y0f));

            const int r0 = y0c * IMG_W;
            const int r1 = y1c * IMG_W;
            const float va = __ldg(img + (r0 + x0c) * IMG_C + c);
            const float vb = __ldg(img + (r1 + x0c) * IMG_C + c);
            const float vc = __ldg(img + (r0 + x1c) * IMG_C + c);
            const float vd = __ldg(img + (r1 + x1c) * IMG_C + c);

            // (((wa*va + wb*vb) + wc*vc) + wd*vd), no contraction
            float o = __fmul_rn(wa, va);
            o = __fadd_rn(o, __fmul_rn(wb, vb));
            o = __fadd_rn(o, __fmul_rn(wc, vc));
            o = __fadd_rn(o, __fmul_rn(wd, vd));
            ob[i * TPB + tid] = o;
        }
    }
}

extern "C" void kernel_launch(void* const* d_in, const int* in_sizes, int n_in,
                              void* d_out, int out_size) {
    const float* image        = (const float*)d_in[0];
    const float* dest_offsets = (const float*)d_in[1];
    const float* right_mat    = (const float*)d_in[2];
    const float* L_inv        = (const float*)d_in[3];
    const float* src          = (const float*)d_in[4];
    float* out = (float*)d_out;

    tps_warp_kernel<<<NUNITS, TPB>>>(image, dest_offsets, right_mat, L_inv, src, out);
}